// round 5
// baseline (speedup 1.0000x reference)
#include <cuda_runtime.h>

// Batched Kabsch RMSD — single fused kernel.
// One warp per row: 16 atoms/thread, 2 phases x 12 independent LDG.128,
// 17-moment butterfly reduce, fp32 3x3 eigen epilogue on lane 0.

constexpr int BATCH = 8192;
constexpr int ROWF4 = 384;   // 1536 floats = 384 float4 per row

__device__ __forceinline__ void accum_atom(float* acc,
                                           float sx, float sy, float sz,
                                           float dx, float dy, float dz)
{
    acc[0] += sx;  acc[1] += sy;  acc[2] += sz;
    acc[3] += dx;  acc[4] += dy;  acc[5] += dz;
    acc[6]  = fmaf(sx, dx, acc[6]);   acc[7]  = fmaf(sx, dy, acc[7]);   acc[8]  = fmaf(sx, dz, acc[8]);
    acc[9]  = fmaf(sy, dx, acc[9]);   acc[10] = fmaf(sy, dy, acc[10]);  acc[11] = fmaf(sy, dz, acc[11]);
    acc[12] = fmaf(sz, dx, acc[12]);  acc[13] = fmaf(sz, dy, acc[13]);  acc[14] = fmaf(sz, dz, acc[14]);
    acc[15] = fmaf(sx, sx, fmaf(sy, sy, fmaf(sz, sz, acc[15])));
    acc[16] = fmaf(dx, dx, fmaf(dy, dy, fmaf(dz, dz, acc[16])));
}

// extract float component `idx` (0..23) from an array of 6 float4 (constant idx)
__device__ __forceinline__ float f4get(const float4* v, int idx)
{
    const float4 q = v[idx >> 2];
    switch (idx & 3) {
        case 0: return q.x;
        case 1: return q.y;
        case 2: return q.z;
        default: return q.w;
    }
}

__global__ __launch_bounds__(32) void kabsch_fused(
    const float* __restrict__ inp,
    const float* __restrict__ tgt,
    const int*   __restrict__ na32,
    float*       __restrict__ out)
{
    const int b = blockIdx.x;
    const int t = threadIdx.x;          // lane 0..31, owns atoms 16t..16t+15

    const float4* s4 = reinterpret_cast<const float4*>(inp) + (size_t)b * ROWF4 + 12 * t;
    const float4* d4 = reinterpret_cast<const float4*>(tgt) + (size_t)b * ROWF4 + 12 * t;

    // num_atoms dtype probe: values always >= 16, so word1==0 <=> int64 layout
    int n;
    {
        const int probe = __ldg(&na32[1]);
        n = (probe == 0) ? __ldg(&na32[2 * b]) : __ldg(&na32[b]);
    }

    float acc[17];
#pragma unroll
    for (int i = 0; i < 17; ++i) acc[i] = 0.0f;

    const int a0 = 16 * t;

#pragma unroll
    for (int ph = 0; ph < 2; ++ph) {
        // 12 independent 16B loads, front-batched for MLP
        float4 S[6], D[6];
#pragma unroll
        for (int i = 0; i < 6; ++i) S[i] = s4[6 * ph + i];
#pragma unroll
        for (int i = 0; i < 6; ++i) D[i] = d4[6 * ph + i];

#pragma unroll
        for (int k = 0; k < 8; ++k) {
            const int a = a0 + 8 * ph + k;
            if (a < n) {
                accum_atom(acc,
                           f4get(S, 3 * k + 0), f4get(S, 3 * k + 1), f4get(S, 3 * k + 2),
                           f4get(D, 3 * k + 0), f4get(D, 3 * k + 1), f4get(D, 3 * k + 2));
            }
        }
    }

    // warp butterfly reduction (17 values)
#pragma unroll
    for (int o = 16; o > 0; o >>= 1) {
#pragma unroll
        for (int i = 0; i < 17; ++i)
            acc[i] += __shfl_xor_sync(0xffffffffu, acc[i], o);
    }

    // ---- fused fp32 epilogue on lane 0 ----
    if (t == 0) {
        const float inv = 1.0f / (float)n;

        // centered correlation matrix R = M - (sum_s)(sum_d)^T / n
        float R[3][3];
#pragma unroll
        for (int i = 0; i < 3; ++i)
#pragma unroll
            for (int j = 0; j < 3; ++j)
                R[i][j] = acc[6 + 3 * i + j] - acc[i] * acc[3 + j] * inv;

        const float sq = acc[15] + acc[16]
            - (acc[0] * acc[0] + acc[1] * acc[1] + acc[2] * acc[2]) * inv
            - (acc[3] * acc[3] + acc[4] * acc[4] + acc[5] * acc[5]) * inv;

        const float detR =
              R[0][0] * (R[1][1] * R[2][2] - R[1][2] * R[2][1])
            - R[0][1] * (R[1][0] * R[2][2] - R[1][2] * R[2][0])
            + R[0][2] * (R[1][0] * R[2][1] - R[1][1] * R[2][0]);

        // A = R^T R (symmetric PSD); singular values of R = sqrt(eig(A))
        const float A00 = R[0][0]*R[0][0] + R[1][0]*R[1][0] + R[2][0]*R[2][0];
        const float A11 = R[0][1]*R[0][1] + R[1][1]*R[1][1] + R[2][1]*R[2][1];
        const float A22 = R[0][2]*R[0][2] + R[1][2]*R[1][2] + R[2][2]*R[2][2];
        const float A01 = R[0][0]*R[0][1] + R[1][0]*R[1][1] + R[2][0]*R[2][1];
        const float A02 = R[0][0]*R[0][2] + R[1][0]*R[1][2] + R[2][0]*R[2][2];
        const float A12 = R[0][1]*R[0][2] + R[1][1]*R[1][2] + R[2][1]*R[2][2];

        const float q  = (A00 + A11 + A22) * (1.0f / 3.0f);
        const float p1 = A01 * A01 + A02 * A02 + A12 * A12;
        const float b0 = A00 - q, b1 = A11 - q, b2 = A22 - q;
        const float p2 = b0 * b0 + b1 * b1 + b2 * b2 + 2.0f * p1;

        float e1, e2, e3;
        if (p2 <= 1e-12f) {
            e1 = e2 = e3 = q;
        } else {
            const float p   = sqrtf(p2 * (1.0f / 6.0f));
            const float ip  = 1.0f / p;
            const float B00 = b0 * ip, B11 = b1 * ip, B22 = b2 * ip;
            const float B01 = A01 * ip, B02 = A02 * ip, B12 = A12 * ip;
            float r =
                ( B00 * (B11 * B22 - B12 * B12)
                - B01 * (B01 * B22 - B12 * B02)
                + B02 * (B01 * B12 - B11 * B02) ) * 0.5f;
            r = fminf(1.0f, fmaxf(-1.0f, r));
            const float phi = acosf(r) * (1.0f / 3.0f);
            const float c1 = __cosf(phi);
            const float c3 = __cosf(phi + 2.0943951023931953f); // + 2*pi/3
            e1 = q + 2.0f * p * c1;
            e3 = q + 2.0f * p * c3;
            e2 = 3.0f * q - e1 - e3;
        }

        const float s1 = sqrtf(fmaxf(e1, 0.0f));   // largest
        const float s2 = sqrtf(fmaxf(e2, 0.0f));
        const float s3 = sqrtf(fmaxf(e3, 0.0f));   // smallest

        const float dsign = (detR >= 0.0f) ? 1.0f : -1.0f;
        const float trace_opt = s1 + s2 + dsign * s3;

        const float msd = (sq - 2.0f * trace_opt) * inv;
        out[b] = sqrtf(fmaxf(msd, 0.0f));
    }
}

extern "C" void kernel_launch(void* const* d_in, const int* in_sizes, int n_in,
                              void* d_out, int out_size)
{
    const float* inp  = (const float*)d_in[0];
    const float* tgt  = (const float*)d_in[1];
    const int*   na32 = (const int*)d_in[2];
    float*       out  = (float*)d_out;

    kabsch_fused<<<BATCH, 32>>>(inp, tgt, na32, out);
}

// round 6
// speedup vs baseline: 1.0695x; 1.0695x over previous
#include <cuda_runtime.h>

// Batched Kabsch RMSD — single fused kernel.
// One 128-thread CTA per row: 4 atoms/thread (3 contiguous float4 per tensor),
// warp butterfly + 4-warp smem combine, fp32 3x3 eigen epilogue on thread 0.

constexpr int BATCH = 8192;
constexpr int ROWF4 = 384;   // 1536 floats = 384 float4 per row
constexpr int TPB   = 128;
constexpr int NW    = TPB / 32;

__device__ __forceinline__ void accum_atom(float* acc,
                                           float sx, float sy, float sz,
                                           float dx, float dy, float dz)
{
    acc[0] += sx;  acc[1] += sy;  acc[2] += sz;
    acc[3] += dx;  acc[4] += dy;  acc[5] += dz;
    acc[6]  = fmaf(sx, dx, acc[6]);   acc[7]  = fmaf(sx, dy, acc[7]);   acc[8]  = fmaf(sx, dz, acc[8]);
    acc[9]  = fmaf(sy, dx, acc[9]);   acc[10] = fmaf(sy, dy, acc[10]);  acc[11] = fmaf(sy, dz, acc[11]);
    acc[12] = fmaf(sz, dx, acc[12]);  acc[13] = fmaf(sz, dy, acc[13]);  acc[14] = fmaf(sz, dz, acc[14]);
    acc[15] = fmaf(sx, sx, fmaf(sy, sy, fmaf(sz, sz, acc[15])));
    acc[16] = fmaf(dx, dx, fmaf(dy, dy, fmaf(dz, dz, acc[16])));
}

__global__ __launch_bounds__(TPB) void kabsch_fused(
    const float* __restrict__ inp,
    const float* __restrict__ tgt,
    const int*   __restrict__ na32,
    float*       __restrict__ out)
{
    __shared__ float s_red[NW][17];

    const int b = blockIdx.x;
    const int t = threadIdx.x;

    // thread t owns atoms 4t..4t+3 == float4 indices 3t..3t+2 (12 contiguous floats)
    const float4* src4 = reinterpret_cast<const float4*>(inp) + (size_t)b * ROWF4 + 3 * t;
    const float4* dst4 = reinterpret_cast<const float4*>(tgt) + (size_t)b * ROWF4 + 3 * t;
    const float4 s0 = src4[0], s1 = src4[1], s2 = src4[2];
    const float4 d0 = dst4[0], d1 = dst4[1], d2 = dst4[2];

    // num_atoms dtype probe: values always >= 16, so word1==0 <=> int64 layout
    int n;
    {
        const int probe = __ldg(&na32[1]);
        n = (probe == 0) ? __ldg(&na32[2 * b]) : __ldg(&na32[b]);
    }

    float acc[17];
#pragma unroll
    for (int i = 0; i < 17; ++i) acc[i] = 0.0f;

    const int a0 = 4 * t;
    if (a0 + 0 < n) accum_atom(acc, s0.x, s0.y, s0.z, d0.x, d0.y, d0.z);
    if (a0 + 1 < n) accum_atom(acc, s0.w, s1.x, s1.y, d0.w, d1.x, d1.y);
    if (a0 + 2 < n) accum_atom(acc, s1.z, s1.w, s2.x, d1.z, d1.w, d2.x);
    if (a0 + 3 < n) accum_atom(acc, s2.y, s2.z, s2.w, d2.y, d2.z, d2.w);

    // warp butterfly reduction (17 values)
#pragma unroll
    for (int o = 16; o > 0; o >>= 1) {
#pragma unroll
        for (int i = 0; i < 17; ++i)
            acc[i] += __shfl_xor_sync(0xffffffffu, acc[i], o);
    }
    const int wid = t >> 5;
    if ((t & 31) == 0) {
#pragma unroll
        for (int i = 0; i < 17; ++i) s_red[wid][i] = acc[i];
    }
    __syncthreads();

    // ---- fused fp32 epilogue on thread 0 ----
    if (t == 0) {
        float v[17];
#pragma unroll
        for (int i = 0; i < 17; ++i)
            v[i] = s_red[0][i] + s_red[1][i] + s_red[2][i] + s_red[3][i];

        const float inv = 1.0f / (float)n;

        // centered correlation matrix R = M - (sum_s)(sum_d)^T / n
        float R[3][3];
#pragma unroll
        for (int i = 0; i < 3; ++i)
#pragma unroll
            for (int j = 0; j < 3; ++j)
                R[i][j] = v[6 + 3 * i + j] - v[i] * v[3 + j] * inv;

        const float sq = v[15] + v[16]
            - (v[0] * v[0] + v[1] * v[1] + v[2] * v[2]) * inv
            - (v[3] * v[3] + v[4] * v[4] + v[5] * v[5]) * inv;

        const float detR =
              R[0][0] * (R[1][1] * R[2][2] - R[1][2] * R[2][1])
            - R[0][1] * (R[1][0] * R[2][2] - R[1][2] * R[2][0])
            + R[0][2] * (R[1][0] * R[2][1] - R[1][1] * R[2][0]);

        // A = R^T R (symmetric PSD); singular values of R = sqrt(eig(A))
        const float A00 = R[0][0]*R[0][0] + R[1][0]*R[1][0] + R[2][0]*R[2][0];
        const float A11 = R[0][1]*R[0][1] + R[1][1]*R[1][1] + R[2][1]*R[2][1];
        const float A22 = R[0][2]*R[0][2] + R[1][2]*R[1][2] + R[2][2]*R[2][2];
        const float A01 = R[0][0]*R[0][1] + R[1][0]*R[1][1] + R[2][0]*R[2][1];
        const float A02 = R[0][0]*R[0][2] + R[1][0]*R[1][2] + R[2][0]*R[2][2];
        const float A12 = R[0][1]*R[0][2] + R[1][1]*R[1][2] + R[2][1]*R[2][2];

        const float q  = (A00 + A11 + A22) * (1.0f / 3.0f);
        const float p1 = A01 * A01 + A02 * A02 + A12 * A12;
        const float b0 = A00 - q, b1 = A11 - q, b2 = A22 - q;
        const float p2 = b0 * b0 + b1 * b1 + b2 * b2 + 2.0f * p1;

        float e1, e2, e3;
        if (p2 <= 1e-12f) {
            e1 = e2 = e3 = q;
        } else {
            const float p   = sqrtf(p2 * (1.0f / 6.0f));
            const float ip  = 1.0f / p;
            const float B00 = b0 * ip, B11 = b1 * ip, B22 = b2 * ip;
            const float B01 = A01 * ip, B02 = A02 * ip, B12 = A12 * ip;
            float r =
                ( B00 * (B11 * B22 - B12 * B12)
                - B01 * (B01 * B22 - B12 * B02)
                + B02 * (B01 * B12 - B11 * B02) ) * 0.5f;
            r = fminf(1.0f, fmaxf(-1.0f, r));
            const float phi = acosf(r) * (1.0f / 3.0f);
            const float c1 = __cosf(phi);
            const float c3 = __cosf(phi + 2.0943951023931953f); // + 2*pi/3
            e1 = q + 2.0f * p * c1;
            e3 = q + 2.0f * p * c3;
            e2 = 3.0f * q - e1 - e3;
        }

        const float s1 = sqrtf(fmaxf(e1, 0.0f));   // largest
        const float s2 = sqrtf(fmaxf(e2, 0.0f));
        const float s3 = sqrtf(fmaxf(e3, 0.0f));   // smallest

        const float dsign = (detR >= 0.0f) ? 1.0f : -1.0f;
        const float trace_opt = s1 + s2 + dsign * s3;

        const float msd = (sq - 2.0f * trace_opt) * inv;
        out[b] = sqrtf(fmaxf(msd, 0.0f));
    }
}

extern "C" void kernel_launch(void* const* d_in, const int* in_sizes, int n_in,
                              void* d_out, int out_size)
{
    const float* inp  = (const float*)d_in[0];
    const float* tgt  = (const float*)d_in[1];
    const int*   na32 = (const int*)d_in[2];
    float*       out  = (float*)d_out;

    kabsch_fused<<<BATCH, TPB>>>(inp, tgt, na32, out);
}